// round 2
// baseline (speedup 1.0000x reference)
#include <cuda_runtime.h>
#include <cstdint>
#include <cstddef>

#define N_TOK 32768
#define DIM   512
#define NCODE 4096
#define NQ    4

// ---------------- device-global scratch (no allocations allowed) ----------------
__device__ float  g_residual[N_TOK * DIM];   // 64 MB
__device__ int    g_idx[N_TOK];
__device__ float  g_rnorm[N_TOK];            // per-token ||r||^2 (fp32), per stage
__device__ double g_loss[NQ];

// ---------------- packed f32x2 helpers (FFMA2 is PTX-only on sm_103a) -----------
__device__ __forceinline__ unsigned long long pack2(float a, float b) {
    unsigned long long r;
    asm("mov.b64 %0, {%1,%2};" : "=l"(r) : "f"(a), "f"(b));
    return r;
}
__device__ __forceinline__ void fma2(unsigned long long& d,
                                     unsigned long long a, unsigned long long b) {
    asm("fma.rn.f32x2 %0, %1, %2, %0;" : "+l"(d) : "l"(a), "l"(b));
}
__device__ __forceinline__ float2 unpack2(unsigned long long v) {
    float lo, hi;
    asm("mov.b64 {%0,%1}, %2;" : "=f"(lo), "=f"(hi) : "l"(v));
    return make_float2(lo, hi);
}

// smem: Rs[512][64] + Cs[32][128] + RN[64] + redV[16*64] + redI[16*64]
#define SMEM_FLOATS (32768 + 4096 + 64 + 1024 + 1024)
#define SMEM_BYTES  (SMEM_FLOATS * 4)

// ---------------- fused GEMM + argmin: one block = 64 tokens x all 4096 codes ----
// Score replicates reference fp32 semantics exactly:
//   dist = round( rnorm - 2*dot ),  dot = sequential-d fp32 FMA chain (Eigen order),
//   (||c||^2 is absorbed by rounding: ||c||^2 ~ 1e-5 < half-ulp(rnorm~512) = 3.05e-5)
//   argmin tie-break = lowest index.
__global__ void __launch_bounds__(256, 1)
argmin_kernel(const float* __restrict__ cb,   // codebook for this stage [NCODE][DIM]
              int stage,
              float* __restrict__ idxf)       // d_out index region (float), stride NQ
{
    extern __shared__ float sm[];
    float* Rs   = sm;                  // d-major, XOR-swizzled, [512][64]
    float* Cs   = sm + 32768;          // d-major, XOR-swizzled, [32][128]
    float* RN   = Cs + 4096;           // 64 token rnorms
    float* redV = RN + 64;             // [16][64]
    int*   redI = (int*)(redV + 1024); // [16][64]

    const int tid = threadIdx.x;
    const int tx  = tid & 15;          // code direction (16)
    const int ty  = tid >> 4;          // token direction (16), 4 tokens each
    const int n0  = blockIdx.x * 64;

    if (tid < 64) RN[tid] = g_rnorm[n0 + tid];

    // Load residual tile [64 tokens x 512 d] -> Rs[d][m], swizzled (conflict-free STS/LDS).
    for (int f = tid; f < 64 * 128; f += 256) {
        const int m  = f >> 7;        // token 0..63
        const int dg = f & 127;       // d-group 0..127
        const float4 v = *reinterpret_cast<const float4*>(
            &g_residual[(size_t)(n0 + m) * DIM + dg * 4]);
        const float vv[4] = {v.x, v.y, v.z, v.w};
#pragma unroll
        for (int j = 0; j < 4; j++) {
            const int d = dg * 4 + j;
            Rs[d * 64 + ((((m >> 2) ^ d) & 15) << 2) + (m & 3)] = vv[j];
        }
    }

    float rn4[4];
    float bestV[4];
    int   bestI[4];
#pragma unroll
    for (int i = 0; i < 4; i++) { bestV[i] = 3.4e38f; bestI[i] = 0; }

    for (int kc = 0; kc < NCODE; kc += 128) {
        unsigned long long acc[16];
#pragma unroll
        for (int i = 0; i < 16; i++) acc[i] = 0ull;

        for (int dk = 0; dk < DIM; dk += 32) {
            __syncthreads();  // previous Cs consumers done (also covers Rs/RN first time)
            // Load Cs chunk [128 codes x 32 d] -> Cs[d][k], swizzled.
#pragma unroll
            for (int i = 0; i < 4; i++) {
                const int f  = tid + i * 256;   // 0..1023
                const int k  = f >> 3;          // code 0..127
                const int dg = f & 7;           // 0..7
                const float4 v = *reinterpret_cast<const float4*>(
                    &cb[(size_t)(kc + k) * DIM + dk + dg * 4]);
                const float vv[4] = {v.x, v.y, v.z, v.w};
#pragma unroll
                for (int j = 0; j < 4; j++) {
                    const int d = dg * 4 + j;   // local d 0..31
                    Cs[d * 128 + ((((k >> 2) ^ d) & 31) << 2) + (k & 3)] = vv[j];
                }
            }
            __syncthreads();

#pragma unroll
            for (int dd = 0; dd < 32; dd++) {
                const int d = dk + dd;
                const float4 rv = *reinterpret_cast<const float4*>(
                    &Rs[d * 64 + (((ty ^ d) & 15) << 2)]);
                const float4 c0 = *reinterpret_cast<const float4*>(
                    &Cs[dd * 128 + (((tx ^ dd) & 31) << 2)]);
                const float4 c1 = *reinterpret_cast<const float4*>(
                    &Cs[dd * 128 + ((((tx + 16) ^ dd) & 31) << 2)]);

                const unsigned long long rp0 = pack2(rv.x, rv.x);
                const unsigned long long rp1 = pack2(rv.y, rv.y);
                const unsigned long long rp2 = pack2(rv.z, rv.z);
                const unsigned long long rp3 = pack2(rv.w, rv.w);
                const unsigned long long cp0 = pack2(c0.x, c0.y);
                const unsigned long long cp1 = pack2(c0.z, c0.w);
                const unsigned long long cp2 = pack2(c1.x, c1.y);
                const unsigned long long cp3 = pack2(c1.z, c1.w);

                fma2(acc[ 0], rp0, cp0); fma2(acc[ 1], rp0, cp1);
                fma2(acc[ 2], rp0, cp2); fma2(acc[ 3], rp0, cp3);
                fma2(acc[ 4], rp1, cp0); fma2(acc[ 5], rp1, cp1);
                fma2(acc[ 6], rp1, cp2); fma2(acc[ 7], rp1, cp3);
                fma2(acc[ 8], rp2, cp0); fma2(acc[ 9], rp2, cp1);
                fma2(acc[10], rp2, cp2); fma2(acc[11], rp2, cp3);
                fma2(acc[12], rp3, cp0); fma2(acc[13], rp3, cp1);
                fma2(acc[14], rp3, cp2); fma2(acc[15], rp3, cp3);
            }
        }

        if (kc == 0) {
#pragma unroll
            for (int m = 0; m < 4; m++) rn4[m] = RN[ty * 4 + m];
        }

        // Epilogue: score = round(rnorm - 2*dot); ascending code order => first-min tie-break.
#pragma unroll
        for (int m = 0; m < 4; m++) {
#pragma unroll
            for (int p = 0; p < 4; p++) {
                const float2 s = unpack2(acc[m * 4 + p]);
                const int klocal = (p >> 1) * 64 + tx * 4 + (p & 1) * 2;
                const float s0 = fmaf(-2.f, s.x, rn4[m]);
                const float s1 = fmaf(-2.f, s.y, rn4[m]);
                if (s0 < bestV[m]) { bestV[m] = s0; bestI[m] = kc + klocal; }
                if (s1 < bestV[m]) { bestV[m] = s1; bestI[m] = kc + klocal + 1; }
            }
        }
    }

    __syncthreads();
#pragma unroll
    for (int i = 0; i < 4; i++) {
        redV[tx * 64 + ty * 4 + i] = bestV[i];
        redI[tx * 64 + ty * 4 + i] = bestI[i];
    }
    __syncthreads();
    if (tid < 64) {
        float bv = redV[tid];
        int   bi = redI[tid];
#pragma unroll
        for (int x = 1; x < 16; x++) {
            const float v = redV[x * 64 + tid];
            const int  ii = redI[x * 64 + tid];
            if (v < bv || (v == bv && ii < bi)) { bv = v; bi = ii; }
        }
        const int n = n0 + tid;
        g_idx[n] = bi;
        idxf[(size_t)n * NQ + stage] = (float)bi;
    }
}

// ------- per-token: residual update + z_q accumulate + loss + next-stage rnorm ---
__global__ void __launch_bounds__(128)
update_kernel(const float* __restrict__ cb, int stage, float* __restrict__ zq)
{
    const int n  = blockIdx.x;                 // token
    const int j  = threadIdx.x;                // 0..127 -> d = 4j
    const size_t off = (size_t)n * DIM + j * 4;

    float4 r = *reinterpret_cast<float4*>(&g_residual[off]);
    const int k = g_idx[n];
    const float4 c = *reinterpret_cast<const float4*>(&cb[(size_t)k * DIM + j * 4]);

    float4 rn = make_float4(r.x - c.x, r.y - c.y, r.z - c.z, r.w - c.w);
    *reinterpret_cast<float4*>(&g_residual[off]) = rn;

    float4 zo;
    if (stage == 0) {
        zo = c;
    } else {
        zo = *reinterpret_cast<float4*>(&zq[off]);
        zo.x += c.x; zo.y += c.y; zo.z += c.z; zo.w += c.w;
    }
    *reinterpret_cast<float4*>(&zq[off]) = zo;

    // next-stage rnorm (fp32, order-insensitive up to harmless ulp shifts)
    float rs = fmaf(rn.x, rn.x, fmaf(rn.y, rn.y, fmaf(rn.z, rn.z, rn.w * rn.w)));
    // loss term on UPDATED residual: (c - r_new)^2
    const float4 tt = make_float4(c.x - rn.x, c.y - rn.y, c.z - rn.z, c.w - rn.w);
    float ls = tt.x * tt.x + tt.y * tt.y + tt.z * tt.z + tt.w * tt.w;
#pragma unroll
    for (int o = 16; o > 0; o >>= 1) {
        rs += __shfl_down_sync(0xffffffffu, rs, o);
        ls += __shfl_down_sync(0xffffffffu, ls, o);
    }
    __shared__ float wr[4], wl[4];
    if ((j & 31) == 0) { wr[j >> 5] = rs; wl[j >> 5] = ls; }
    __syncthreads();
    if (j == 0) {
        g_rnorm[n] = (wr[0] + wr[1]) + (wr[2] + wr[3]);
        atomicAdd(&g_loss[stage], (double)((wl[0] + wl[1]) + (wl[2] + wl[3])));
    }
}

// ---------------- straight-through: z_q = z + (z_q - z), reference fp order -----
__global__ void __launch_bounds__(256)
ste_kernel(const float* __restrict__ z, float* __restrict__ zq)
{
    const int t = blockIdx.x * 256 + threadIdx.x;
    const float4 zv = reinterpret_cast<const float4*>(z)[t];
    float4 q = reinterpret_cast<float4*>(zq)[t];
    q.x = zv.x + (q.x - zv.x);
    q.y = zv.y + (q.y - zv.y);
    q.z = zv.z + (q.z - zv.z);
    q.w = zv.w + (q.w - zv.w);
    reinterpret_cast<float4*>(zq)[t] = q;
}

// ------- init: residual = z, rnorm(z), loss reset (one block per token) ---------
__global__ void __launch_bounds__(128)
init_kernel(const float* __restrict__ z)
{
    const int n = blockIdx.x;
    const int j = threadIdx.x;
    if (n == 0 && j < NQ) g_loss[j] = 0.0;
    const size_t off = (size_t)n * DIM + j * 4;
    const float4 v = *reinterpret_cast<const float4*>(&z[off]);
    *reinterpret_cast<float4*>(&g_residual[off]) = v;
    float rs = fmaf(v.x, v.x, fmaf(v.y, v.y, fmaf(v.z, v.z, v.w * v.w)));
#pragma unroll
    for (int o = 16; o > 0; o >>= 1) rs += __shfl_down_sync(0xffffffffu, rs, o);
    __shared__ float wr[4];
    if ((j & 31) == 0) wr[j >> 5] = rs;
    __syncthreads();
    if (j == 0) g_rnorm[n] = (wr[0] + wr[1]) + (wr[2] + wr[3]);
}

__global__ void finalize_kernel(float* __restrict__ outloss)
{
    double t = 0.0;
#pragma unroll
    for (int s = 0; s < NQ; s++) t += 1.25 * (g_loss[s] / 16777216.0);
    *outloss = (float)t;
}

// ---------------- launch --------------------------------------------------------
extern "C" void kernel_launch(void* const* d_in, const int* in_sizes, int n_in,
                              void* d_out, int out_size)
{
    const float* z   = (const float*)d_in[0];   // [16,2048,512] f32
    const float* cbs = (const float*)d_in[1];   // [4,4096,512]  f32
    float* out  = (float*)d_out;
    float* zq   = out;                                        // 16,777,216
    float* idxf = out + (size_t)N_TOK * DIM;                  // 131,072
    float* lossp = idxf + (size_t)N_TOK * NQ;                 // 1

    cudaFuncSetAttribute(argmin_kernel,
                         cudaFuncAttributeMaxDynamicSharedMemorySize, SMEM_BYTES);

    init_kernel<<<N_TOK, 128>>>(z);

    for (int s = 0; s < NQ; s++) {
        const float* cb_s = cbs + (size_t)s * NCODE * DIM;
        argmin_kernel<<<N_TOK / 64, 256, SMEM_BYTES>>>(cb_s, s, idxf);
        update_kernel<<<N_TOK, 128>>>(cb_s, s, zq);
    }
    ste_kernel<<<(N_TOK * DIM / 4) / 256, 256>>>(z, zq);
    finalize_kernel<<<1, 1>>>(lossp);
}

// round 3
// speedup vs baseline: 1.0505x; 1.0505x over previous
#include <cuda_runtime.h>
#include <cstdint>
#include <cstddef>

#define N_TOK 32768
#define DIM   512
#define NCODE 4096
#define NQ    4

// ---------------- device-global scratch (no allocations allowed) ----------------
__device__ float  g_residual[N_TOK * DIM];   // 64 MB
__device__ int    g_idx[N_TOK];
__device__ float  g_rnorm[N_TOK];            // per-token ||r||^2 (fp32), per stage
__device__ double g_loss[NQ];

// ---------------- packed f32x2 helpers (FFMA2 is PTX-only on sm_103a) -----------
__device__ __forceinline__ unsigned long long pack2(float a, float b) {
    unsigned long long r;
    asm("mov.b64 %0, {%1,%2};" : "=l"(r) : "f"(a), "f"(b));
    return r;
}
__device__ __forceinline__ void fma2(unsigned long long& d,
                                     unsigned long long a, unsigned long long b) {
    asm("fma.rn.f32x2 %0, %1, %2, %0;" : "+l"(d) : "l"(a), "l"(b));
}
__device__ __forceinline__ float2 unpack2(unsigned long long v) {
    float lo, hi;
    asm("mov.b64 {%0,%1}, %2;" : "=f"(lo), "=f"(hi) : "l"(v));
    return make_float2(lo, hi);
}

// smem: Rs[512][64] + Cs[32][128] + RN[64] + redV[16*64] + redI[16*64]
#define SMEM_FLOATS (32768 + 4096 + 64 + 1024 + 1024)
#define SMEM_BYTES  (SMEM_FLOATS * 4)

// ---------------- fused GEMM + argmin: one block = 64 tokens x all 4096 codes ----
// Score replicates reference fp32 semantics exactly:
//   dist = round( rnorm - 2*dot ),  dot = sequential-d fp32 FMA chain (Eigen order),
//   (||c||^2 is absorbed by rounding: ||c||^2 ~ 1e-5 < half-ulp(rnorm~512) = 3.05e-5)
//   argmin tie-break = lowest index.
__global__ void __launch_bounds__(256, 1)
argmin_kernel(const float* __restrict__ cb,   // codebook for this stage [NCODE][DIM]
              int stage,
              float* __restrict__ idxf)       // d_out index region (float), stride NQ
{
    extern __shared__ float sm[];
    float* Rs   = sm;                  // d-major, XOR-swizzled, [512][64]
    float* Cs   = sm + 32768;          // d-major, XOR-swizzled, [32][128]
    float* RN   = Cs + 4096;           // 64 token rnorms
    float* redV = RN + 64;             // [16][64]
    int*   redI = (int*)(redV + 1024); // [16][64]

    const int tid = threadIdx.x;
    const int tx  = tid & 15;          // code direction (16)
    const int ty  = tid >> 4;          // token direction (16), 4 tokens each
    const int n0  = blockIdx.x * 64;

    if (tid < 64) RN[tid] = g_rnorm[n0 + tid];

    // Load residual tile [64 tokens x 512 d] -> Rs[d][m], swizzled (conflict-free STS/LDS).
    for (int f = tid; f < 64 * 128; f += 256) {
        const int m  = f >> 7;        // token 0..63
        const int dg = f & 127;       // d-group 0..127
        const float4 v = *reinterpret_cast<const float4*>(
            &g_residual[(size_t)(n0 + m) * DIM + dg * 4]);
        const float vv[4] = {v.x, v.y, v.z, v.w};
#pragma unroll
        for (int j = 0; j < 4; j++) {
            const int d = dg * 4 + j;
            Rs[d * 64 + ((((m >> 2) ^ d) & 15) << 2) + (m & 3)] = vv[j];
        }
    }

    float rn4[4];
    float bestV[4];
    int   bestI[4];
#pragma unroll
    for (int i = 0; i < 4; i++) { bestV[i] = 3.4e38f; bestI[i] = 0; }

    for (int kc = 0; kc < NCODE; kc += 128) {
        unsigned long long acc[16];
#pragma unroll
        for (int i = 0; i < 16; i++) acc[i] = 0ull;

        for (int dk = 0; dk < DIM; dk += 32) {
            __syncthreads();  // previous Cs consumers done (also covers Rs/RN first time)
            // Load Cs chunk [128 codes x 32 d] -> Cs[d][k], swizzled.
#pragma unroll
            for (int i = 0; i < 4; i++) {
                const int f  = tid + i * 256;   // 0..1023
                const int k  = f >> 3;          // code 0..127
                const int dg = f & 7;           // 0..7
                const float4 v = *reinterpret_cast<const float4*>(
                    &cb[(size_t)(kc + k) * DIM + dk + dg * 4]);
                const float vv[4] = {v.x, v.y, v.z, v.w};
#pragma unroll
                for (int j = 0; j < 4; j++) {
                    const int d = dg * 4 + j;   // local d 0..31
                    Cs[d * 128 + ((((k >> 2) ^ d) & 31) << 2) + (k & 3)] = vv[j];
                }
            }
            __syncthreads();

#pragma unroll
            for (int dd = 0; dd < 32; dd++) {
                const int d = dk + dd;
                const float4 rv = *reinterpret_cast<const float4*>(
                    &Rs[d * 64 + (((ty ^ d) & 15) << 2)]);
                const float4 c0 = *reinterpret_cast<const float4*>(
                    &Cs[dd * 128 + (((tx ^ dd) & 31) << 2)]);
                const float4 c1 = *reinterpret_cast<const float4*>(
                    &Cs[dd * 128 + ((((tx + 16) ^ dd) & 31) << 2)]);

                const unsigned long long rp0 = pack2(rv.x, rv.x);
                const unsigned long long rp1 = pack2(rv.y, rv.y);
                const unsigned long long rp2 = pack2(rv.z, rv.z);
                const unsigned long long rp3 = pack2(rv.w, rv.w);
                const unsigned long long cp0 = pack2(c0.x, c0.y);
                const unsigned long long cp1 = pack2(c0.z, c0.w);
                const unsigned long long cp2 = pack2(c1.x, c1.y);
                const unsigned long long cp3 = pack2(c1.z, c1.w);

                fma2(acc[ 0], rp0, cp0); fma2(acc[ 1], rp0, cp1);
                fma2(acc[ 2], rp0, cp2); fma2(acc[ 3], rp0, cp3);
                fma2(acc[ 4], rp1, cp0); fma2(acc[ 5], rp1, cp1);
                fma2(acc[ 6], rp1, cp2); fma2(acc[ 7], rp1, cp3);
                fma2(acc[ 8], rp2, cp0); fma2(acc[ 9], rp2, cp1);
                fma2(acc[10], rp2, cp2); fma2(acc[11], rp2, cp3);
                fma2(acc[12], rp3, cp0); fma2(acc[13], rp3, cp1);
                fma2(acc[14], rp3, cp2); fma2(acc[15], rp3, cp3);
            }
        }

        if (kc == 0) {
#pragma unroll
            for (int m = 0; m < 4; m++) rn4[m] = RN[ty * 4 + m];
        }

        // Epilogue: score = round(rnorm - 2*dot); ascending code order => first-min tie-break.
#pragma unroll
        for (int m = 0; m < 4; m++) {
#pragma unroll
            for (int p = 0; p < 4; p++) {
                const float2 s = unpack2(acc[m * 4 + p]);
                const int klocal = (p >> 1) * 64 + tx * 4 + (p & 1) * 2;
                const float s0 = fmaf(-2.f, s.x, rn4[m]);
                const float s1 = fmaf(-2.f, s.y, rn4[m]);
                if (s0 < bestV[m]) { bestV[m] = s0; bestI[m] = kc + klocal; }
                if (s1 < bestV[m]) { bestV[m] = s1; bestI[m] = kc + klocal + 1; }
            }
        }
    }

    __syncthreads();
#pragma unroll
    for (int i = 0; i < 4; i++) {
        redV[tx * 64 + ty * 4 + i] = bestV[i];
        redI[tx * 64 + ty * 4 + i] = bestI[i];
    }
    __syncthreads();
    if (tid < 64) {
        float bv = redV[tid];
        int   bi = redI[tid];
#pragma unroll
        for (int x = 1; x < 16; x++) {
            const float v = redV[x * 64 + tid];
            const int  ii = redI[x * 64 + tid];
            if (v < bv || (v == bv && ii < bi)) { bv = v; bi = ii; }
        }
        const int n = n0 + tid;
        g_idx[n] = bi;
        idxf[(size_t)n * NQ + stage] = (float)bi;
    }
}

// ------- per-token: residual update + z_q accumulate + loss + next-stage rnorm ---
__global__ void __launch_bounds__(128)
update_kernel(const float* __restrict__ cb, int stage, float* __restrict__ zq)
{
    const int n  = blockIdx.x;                 // token
    const int j  = threadIdx.x;                // 0..127 -> d = 4j
    const size_t off = (size_t)n * DIM + j * 4;

    float4 r = *reinterpret_cast<float4*>(&g_residual[off]);
    const int k = g_idx[n];
    const float4 c = *reinterpret_cast<const float4*>(&cb[(size_t)k * DIM + j * 4]);

    float4 rn = make_float4(r.x - c.x, r.y - c.y, r.z - c.z, r.w - c.w);
    *reinterpret_cast<float4*>(&g_residual[off]) = rn;

    float4 zo;
    if (stage == 0) {
        zo = c;
    } else {
        zo = *reinterpret_cast<float4*>(&zq[off]);
        zo.x += c.x; zo.y += c.y; zo.z += c.z; zo.w += c.w;
    }
    *reinterpret_cast<float4*>(&zq[off]) = zo;

    // next-stage rnorm (fp32, order-insensitive up to harmless ulp shifts)
    float rs = fmaf(rn.x, rn.x, fmaf(rn.y, rn.y, fmaf(rn.z, rn.z, rn.w * rn.w)));
    // loss term on UPDATED residual: (c - r_new)^2
    const float4 tt = make_float4(c.x - rn.x, c.y - rn.y, c.z - rn.z, c.w - rn.w);
    float ls = tt.x * tt.x + tt.y * tt.y + tt.z * tt.z + tt.w * tt.w;
#pragma unroll
    for (int o = 16; o > 0; o >>= 1) {
        rs += __shfl_down_sync(0xffffffffu, rs, o);
        ls += __shfl_down_sync(0xffffffffu, ls, o);
    }
    __shared__ float wr[4], wl[4];
    if ((j & 31) == 0) { wr[j >> 5] = rs; wl[j >> 5] = ls; }
    __syncthreads();
    if (j == 0) {
        g_rnorm[n] = (wr[0] + wr[1]) + (wr[2] + wr[3]);
        atomicAdd(&g_loss[stage], (double)((wl[0] + wl[1]) + (wl[2] + wl[3])));
    }
}

// ---------------- straight-through: z_q = z + (z_q - z), reference fp order -----
__global__ void __launch_bounds__(256)
ste_kernel(const float* __restrict__ z, float* __restrict__ zq)
{
    const int t = blockIdx.x * 256 + threadIdx.x;
    const float4 zv = reinterpret_cast<const float4*>(z)[t];
    float4 q = reinterpret_cast<float4*>(zq)[t];
    q.x = zv.x + (q.x - zv.x);
    q.y = zv.y + (q.y - zv.y);
    q.z = zv.z + (q.z - zv.z);
    q.w = zv.w + (q.w - zv.w);
    reinterpret_cast<float4*>(zq)[t] = q;
}

// ------- init: residual = z, rnorm(z), loss reset (one block per token) ---------
__global__ void __launch_bounds__(128)
init_kernel(const float* __restrict__ z)
{
    const int n = blockIdx.x;
    const int j = threadIdx.x;
    if (n == 0 && j < NQ) g_loss[j] = 0.0;
    const size_t off = (size_t)n * DIM + j * 4;
    const float4 v = *reinterpret_cast<const float4*>(&z[off]);
    *reinterpret_cast<float4*>(&g_residual[off]) = v;
    float rs = fmaf(v.x, v.x, fmaf(v.y, v.y, fmaf(v.z, v.z, v.w * v.w)));
#pragma unroll
    for (int o = 16; o > 0; o >>= 1) rs += __shfl_down_sync(0xffffffffu, rs, o);
    __shared__ float wr[4];
    if ((j & 31) == 0) wr[j >> 5] = rs;
    __syncthreads();
    if (j == 0) g_rnorm[n] = (wr[0] + wr[1]) + (wr[2] + wr[3]);
}

__global__ void finalize_kernel(float* __restrict__ outloss)
{
    double t = 0.0;
#pragma unroll
    for (int s = 0; s < NQ; s++) t += 1.25 * (g_loss[s] / 16777216.0);
    *outloss = (float)t;
}

// ---------------- launch --------------------------------------------------------
extern "C" void kernel_launch(void* const* d_in, const int* in_sizes, int n_in,
                              void* d_out, int out_size)
{
    const float* z   = (const float*)d_in[0];   // [16,2048,512] f32
    const float* cbs = (const float*)d_in[1];   // [4,4096,512]  f32
    float* out  = (float*)d_out;
    float* zq   = out;                                        // 16,777,216
    float* idxf = out + (size_t)N_TOK * DIM;                  // 131,072
    float* lossp = idxf + (size_t)N_TOK * NQ;                 // 1

    cudaFuncSetAttribute(argmin_kernel,
                         cudaFuncAttributeMaxDynamicSharedMemorySize, SMEM_BYTES);

    init_kernel<<<N_TOK, 128>>>(z);

    for (int s = 0; s < NQ; s++) {
        const float* cb_s = cbs + (size_t)s * NCODE * DIM;
        argmin_kernel<<<N_TOK / 64, 256, SMEM_BYTES>>>(cb_s, s, idxf);
        update_kernel<<<N_TOK, 128>>>(cb_s, s, zq);
    }
    ste_kernel<<<(N_TOK * DIM / 4) / 256, 256>>>(z, zq);
    finalize_kernel<<<1, 1>>>(lossp);
}

// round 4
// speedup vs baseline: 1.6720x; 1.5915x over previous
#include <cuda_runtime.h>
#include <cstdint>
#include <cstddef>

#define N_TOK 32768
#define DIM   512
#define NCODE 4096
#define NQ    4

typedef unsigned long long ull;

// ---------------- device-global scratch (no allocations allowed) ----------------
__device__ float  g_residual[N_TOK * DIM];   // 64 MB
__device__ float  g_rnorm[N_TOK];            // per-token ||r||^2 (fp32), per stage
__device__ float  g_pv[2 * N_TOK];           // per-half best value
__device__ int    g_pi[2 * N_TOK];           // per-half best index
__device__ double g_loss[NQ];

// ---------------- packed f32x2 helpers (FFMA2 is PTX-only on sm_103a) -----------
__device__ __forceinline__ ull pack2(float a, float b) {
    ull r;
    asm("mov.b64 %0, {%1,%2};" : "=l"(r) : "f"(a), "f"(b));
    return r;
}
__device__ __forceinline__ void fma2(ull& d, ull a, ull b) {
    asm("fma.rn.f32x2 %0, %1, %2, %0;" : "+l"(d) : "l"(a), "l"(b));
}
__device__ __forceinline__ float2 unpack2(ull v) {
    float lo, hi;
    asm("mov.b64 {%0,%1}, %2;" : "=f"(lo), "=f"(hi) : "l"(v));
    return make_float2(lo, hi);
}

// smem: Rs[512][64] + Cs[32][256] (XOR-swizzled)
#define SMEM_FLOATS (32768 + 8192)
#define SMEM_BYTES  (SMEM_FLOATS * 4)

__device__ __forceinline__ void prefetch8(const float* __restrict__ p, int tid,
                                          float4* pf) {
#pragma unroll
    for (int i = 0; i < 8; i++) {
        const int f = i * 256 + tid;
        const int k = f >> 3;     // code 0..255
        const int dg = f & 7;     // d-group 0..7
        pf[i] = *reinterpret_cast<const float4*>(&p[(size_t)k * DIM + dg * 4]);
    }
}

// ---------------- fused GEMM + argmin -------------------------------------------
// One block = 64 tokens x 2048 codes (half codebook). 256 threads:
//   tx = tid&31 -> codes {4tx..4tx+3} and {128+4tx..+3} of each 256-code chunk
//   ty = tid>>5 -> tokens ty*8 .. ty*8+7 (r-operand LDS is warp-broadcast)
// Numerics identical to reference: dot = sequential-d fp32 FMA chain,
// score = fmaf(-2, dot, rnorm), tie-break lowest index.
__global__ void __launch_bounds__(256, 1)
argmin_kernel(const float* __restrict__ cb)   // codebook for this stage [NCODE][DIM]
{
    extern __shared__ float sm[];
    float* Rs = sm;            // [512][64]  Rs[d*64+m]
    float* Cs = sm + 32768;    // [32][256]  swizzled: Cs[d*256 + ((k>>2 ^ d>>2)&63)*4 + (k&3)]

    const int tid  = threadIdx.x;
    const int tx   = tid & 31;
    const int ty   = tid >> 5;
    const int n0   = (blockIdx.x >> 1) * 64;
    const int half = blockIdx.x & 1;
    const int k0   = half * (NCODE / 2);

    float rnm[8];
#pragma unroll
    for (int m = 0; m < 8; m++) rnm[m] = g_rnorm[n0 + ty * 8 + m];

    // Fill Rs [64 tokens x 512 d] -> Rs[d][m] (STS conflict-free: contiguous m per warp)
#pragma unroll 4
    for (int it = 0; it < 32; it++) {
        const int f  = it * 256 + tid;
        const int m  = f & 63;
        const int dg = f >> 6;            // 0..127
        const float4 v = *reinterpret_cast<const float4*>(
            &g_residual[(size_t)(n0 + m) * DIM + dg * 4]);
        Rs[(dg * 4 + 0) * 64 + m] = v.x;
        Rs[(dg * 4 + 1) * 64 + m] = v.y;
        Rs[(dg * 4 + 2) * 64 + m] = v.z;
        Rs[(dg * 4 + 3) * 64 + m] = v.w;
    }

    float bestV[8];
    int   bestI[8];
#pragma unroll
    for (int m = 0; m < 8; m++) { bestV[m] = 3.4e38f; bestI[m] = 0; }

    float4 pf[8];
    prefetch8(cb + (size_t)k0 * DIM, tid, pf);

    for (int kc = 0; kc < NCODE / 2; kc += 256) {
        ull acc[32];
#pragma unroll
        for (int i = 0; i < 32; i++) acc[i] = 0ull;

        for (int dk = 0; dk < DIM; dk += 32) {
            __syncthreads();   // previous chunk's Cs consumers done (covers Rs 1st time)

            // Store prefetched chunk [256 codes x 32 d] into swizzled Cs.
#pragma unroll
            for (int i = 0; i < 8; i++) {
                const int f  = i * 256 + tid;
                const int k  = f >> 3;
                const int dg = f & 7;
                const int kg = k >> 2, kq = k & 3;
                const float vv[4] = {pf[i].x, pf[i].y, pf[i].z, pf[i].w};
#pragma unroll
                for (int j = 0; j < 4; j++)
                    Cs[(dg * 4 + j) * 256 + (((kg ^ dg) & 63) << 2) + kq] = vv[j];
            }

            // Prefetch next chunk while computing this one.
            {
                int nkc = kc, ndk = dk + 32;
                if (ndk == DIM) { ndk = 0; nkc = kc + 256; }
                if (nkc < NCODE / 2)
                    prefetch8(cb + (size_t)(k0 + nkc) * DIM + ndk, tid, pf);
            }
            __syncthreads();

#pragma unroll
            for (int dd = 0; dd < 32; dd++) {
                const int d  = dk + dd;
                const int c1 = (tx ^ (dd >> 2));
                const float4 rv0 = *reinterpret_cast<const float4*>(&Rs[d * 64 + ty * 8]);
                const float4 rv1 = *reinterpret_cast<const float4*>(&Rs[d * 64 + ty * 8 + 4]);
                const double2 cA = *reinterpret_cast<const double2*>(&Cs[dd * 256 + (c1 << 2)]);
                const double2 cB = *reinterpret_cast<const double2*>(&Cs[dd * 256 + 128 + (c1 << 2)]);
                const ull cA01 = __double_as_longlong(cA.x);
                const ull cA23 = __double_as_longlong(cA.y);
                const ull cB01 = __double_as_longlong(cB.x);
                const ull cB23 = __double_as_longlong(cB.y);
                const float rr[8] = {rv0.x, rv0.y, rv0.z, rv0.w,
                                     rv1.x, rv1.y, rv1.z, rv1.w};
#pragma unroll
                for (int m = 0; m < 8; m++) {
                    const ull rp = pack2(rr[m], rr[m]);
                    fma2(acc[m * 4 + 0], rp, cA01);
                    fma2(acc[m * 4 + 1], rp, cA23);
                    fma2(acc[m * 4 + 2], rp, cB01);
                    fma2(acc[m * 4 + 3], rp, cB23);
                }
            }
        }

        // Epilogue: score = round(rnorm - 2*dot); ascending code order, strict '<'.
#pragma unroll
        for (int m = 0; m < 8; m++) {
#pragma unroll
            for (int kk = 0; kk < 4; kk++) {
                const float2 s = unpack2(acc[m * 4 + kk]);
                const int base = k0 + kc + ((kk & 2) ? 128 : 0) + tx * 4 + (kk & 1) * 2;
                const float s0 = fmaf(-2.f, s.x, rnm[m]);
                const float s1 = fmaf(-2.f, s.y, rnm[m]);
                if (s0 < bestV[m]) { bestV[m] = s0; bestI[m] = base; }
                if (s1 < bestV[m]) { bestV[m] = s1; bestI[m] = base + 1; }
            }
        }
    }

    // Warp-level (v, i) lexicographic min: all lanes of a warp share the same tokens.
#pragma unroll
    for (int m = 0; m < 8; m++) {
        float v = bestV[m];
        int   i = bestI[m];
#pragma unroll
        for (int o = 16; o > 0; o >>= 1) {
            const float vo = __shfl_down_sync(0xffffffffu, v, o);
            const int   io = __shfl_down_sync(0xffffffffu, i, o);
            if (vo < v || (vo == v && io < i)) { v = vo; i = io; }
        }
        if (tx == 0) {
            const int n = n0 + ty * 8 + m;
            g_pv[half * N_TOK + n] = v;
            g_pi[half * N_TOK + n] = i;
        }
    }
}

// ------- per-token: merge halves, residual update, z_q accumulate, loss, rnorm ---
__global__ void __launch_bounds__(128)
update_kernel(const float* __restrict__ cb, int stage,
              float* __restrict__ zq, float* __restrict__ idxf)
{
    const int n = blockIdx.x;
    const int j = threadIdx.x;

    // merge two halves: half 1 wins only if strictly smaller (lower index on ties)
    const float v0 = g_pv[n], v1 = g_pv[N_TOK + n];
    const int k = (v1 < v0) ? g_pi[N_TOK + n] : g_pi[n];
    if (j == 0) idxf[(size_t)n * NQ + stage] = (float)k;

    const size_t off = (size_t)n * DIM + j * 4;
    const float4 r = *reinterpret_cast<float4*>(&g_residual[off]);
    const float4 c = *reinterpret_cast<const float4*>(&cb[(size_t)k * DIM + j * 4]);

    const float4 rn = make_float4(r.x - c.x, r.y - c.y, r.z - c.z, r.w - c.w);
    if (stage < NQ - 1)
        *reinterpret_cast<float4*>(&g_residual[off]) = rn;

    float4 zo;
    if (stage == 0) {
        zo = c;
    } else {
        zo = *reinterpret_cast<float4*>(&zq[off]);
        zo.x += c.x; zo.y += c.y; zo.z += c.z; zo.w += c.w;
    }
    *reinterpret_cast<float4*>(&zq[off]) = zo;

    // next-stage rnorm + loss on UPDATED residual: (c - r_new)^2
    float rs = fmaf(rn.x, rn.x, fmaf(rn.y, rn.y, fmaf(rn.z, rn.z, rn.w * rn.w)));
    const float4 tt = make_float4(c.x - rn.x, c.y - rn.y, c.z - rn.z, c.w - rn.w);
    float ls = tt.x * tt.x + tt.y * tt.y + tt.z * tt.z + tt.w * tt.w;
#pragma unroll
    for (int o = 16; o > 0; o >>= 1) {
        rs += __shfl_down_sync(0xffffffffu, rs, o);
        ls += __shfl_down_sync(0xffffffffu, ls, o);
    }
    __shared__ float wr[4], wl[4];
    if ((j & 31) == 0) { wr[j >> 5] = rs; wl[j >> 5] = ls; }
    __syncthreads();
    if (j == 0) {
        if (stage < NQ - 1) g_rnorm[n] = (wr[0] + wr[1]) + (wr[2] + wr[3]);
        atomicAdd(&g_loss[stage], (double)((wl[0] + wl[1]) + (wl[2] + wl[3])));
    }
}

// ---------------- straight-through: z_q = z + (z_q - z), reference fp order -----
__global__ void __launch_bounds__(256)
ste_kernel(const float* __restrict__ z, float* __restrict__ zq)
{
    const int t = blockIdx.x * 256 + threadIdx.x;
    const float4 zv = reinterpret_cast<const float4*>(z)[t];
    float4 q = reinterpret_cast<float4*>(zq)[t];
    q.x = zv.x + (q.x - zv.x);
    q.y = zv.y + (q.y - zv.y);
    q.z = zv.z + (q.z - zv.z);
    q.w = zv.w + (q.w - zv.w);
    reinterpret_cast<float4*>(zq)[t] = q;
}

// ------- init: residual = z, rnorm(z), loss reset (one block per token) ---------
__global__ void __launch_bounds__(128)
init_kernel(const float* __restrict__ z)
{
    const int n = blockIdx.x;
    const int j = threadIdx.x;
    if (n == 0 && j < NQ) g_loss[j] = 0.0;
    const size_t off = (size_t)n * DIM + j * 4;
    const float4 v = *reinterpret_cast<const float4*>(&z[off]);
    *reinterpret_cast<float4*>(&g_residual[off]) = v;
    float rs = fmaf(v.x, v.x, fmaf(v.y, v.y, fmaf(v.z, v.z, v.w * v.w)));
#pragma unroll
    for (int o = 16; o > 0; o >>= 1) rs += __shfl_down_sync(0xffffffffu, rs, o);
    __shared__ float wr[4];
    if ((j & 31) == 0) wr[j >> 5] = rs;
    __syncthreads();
    if (j == 0) g_rnorm[n] = (wr[0] + wr[1]) + (wr[2] + wr[3]);
}

__global__ void finalize_kernel(float* __restrict__ outloss)
{
    double t = 0.0;
#pragma unroll
    for (int s = 0; s < NQ; s++) t += 1.25 * (g_loss[s] / 16777216.0);
    *outloss = (float)t;
}

// ---------------- launch --------------------------------------------------------
extern "C" void kernel_launch(void* const* d_in, const int* in_sizes, int n_in,
                              void* d_out, int out_size)
{
    const float* z   = (const float*)d_in[0];   // [16,2048,512] f32
    const float* cbs = (const float*)d_in[1];   // [4,4096,512]  f32
    float* out   = (float*)d_out;
    float* zq    = out;                                       // 16,777,216
    float* idxf  = out + (size_t)N_TOK * DIM;                 // 131,072
    float* lossp = idxf + (size_t)N_TOK * NQ;                 // 1

    cudaFuncSetAttribute(argmin_kernel,
                         cudaFuncAttributeMaxDynamicSharedMemorySize, SMEM_BYTES);

    init_kernel<<<N_TOK, 128>>>(z);

    for (int s = 0; s < NQ; s++) {
        const float* cb_s = cbs + (size_t)s * NCODE * DIM;
        argmin_kernel<<<(N_TOK / 64) * 2, 256, SMEM_BYTES>>>(cb_s);
        update_kernel<<<N_TOK, 128>>>(cb_s, s, zq, idxf);
    }
    ste_kernel<<<(N_TOK * DIM / 4) / 256, 256>>>(z, zq);
    finalize_kernel<<<1, 1>>>(lossp);
}

// round 5
// speedup vs baseline: 1.6896x; 1.0106x over previous
#include <cuda_runtime.h>
#include <cstdint>
#include <cstddef>

#define N_TOK 32768
#define DIM   512
#define NCODE 4096
#define NQ    4

typedef unsigned long long ull;

// ---------------- device-global scratch (no allocations allowed) ----------------
__device__ float  g_residual[N_TOK * DIM];   // 64 MB
__device__ float  g_rnorm[N_TOK];            // per-token ||r||^2 (fp32), per stage
__device__ float  g_pv[2 * N_TOK];           // per-half best value
__device__ int    g_pi[2 * N_TOK];           // per-half best index
__device__ double g_loss[NQ];

// ---------------- packed f32x2 helpers (FFMA2 is PTX-only on sm_103a) -----------
__device__ __forceinline__ ull pack2(float a, float b) {
    ull r;
    asm("mov.b64 %0, {%1,%2};" : "=l"(r) : "f"(a), "f"(b));
    return r;
}
__device__ __forceinline__ void fma2(ull& d, ull a, ull b) {
    asm("fma.rn.f32x2 %0, %1, %2, %0;" : "+l"(d) : "l"(a), "l"(b));
}
__device__ __forceinline__ float2 unpack2(ull v) {
    float lo, hi;
    asm("mov.b64 {%0,%1}, %2;" : "=f"(lo), "=f"(hi) : "l"(v));
    return make_float2(lo, hi);
}

// smem: Rs[512][64] + Cs[2][32][256] (double-buffered, XOR-swizzled) + red arrays
#define RS_FLOATS 32768
#define CS_FLOATS 8192
#define RED_OFF   (RS_FLOATS + 2 * CS_FLOATS)          // 49152
#define SMEM_FLOATS (RED_OFF + 128 + 128)
#define SMEM_BYTES  (SMEM_FLOATS * 4)

__device__ __forceinline__ void prefetch4(const float* __restrict__ p, int tid,
                                          float4* pf) {
#pragma unroll
    for (int i = 0; i < 4; i++) {
        const int f  = i * 512 + tid;
        const int k  = f >> 3;     // code 0..255
        const int dg = f & 7;      // d-group 0..7
        pf[i] = *reinterpret_cast<const float4*>(&p[(size_t)k * DIM + dg * 4]);
    }
}

// ---------------- fused GEMM + argmin -------------------------------------------
// One block = 64 tokens x 2048 codes (half codebook). 512 threads:
//   kid = tid&63  -> codes kid*4..kid*4+3 of each 256-code chunk
//   tg  = tid>>6  -> tokens tg*8 .. tg*8+7 (token-PAIRED accumulators: the r
//                    operand is read from Rs directly as 64-bit pairs, zero packs)
// Numerics identical to reference: dot = sequential-d fp32 FMA chain,
// score = fmaf(-2, dot, rnorm), tie-break lowest index.
__global__ void __launch_bounds__(512, 1)
argmin_kernel(const float* __restrict__ cb)   // codebook for this stage [NCODE][DIM]
{
    extern __shared__ float sm[];
    float* Rs   = sm;                 // [512][64]  Rs[d*64+m]
    float* Cs   = sm + RS_FLOATS;     // 2 x [32][256] swizzled: [d*256 + (k ^ ((d>>2)<<2))]
    float* redV = sm + RED_OFF;       // [16 warps][8 tokens]
    int*   redI = (int*)(redV + 128);

    const int tid  = threadIdx.x;
    const int kid  = tid & 63;
    const int tg   = tid >> 6;
    const int wid  = tid >> 5;
    const int lane = tid & 31;
    const int n0   = (blockIdx.x >> 1) * 64;
    const int half = blockIdx.x & 1;
    const int k0   = half * (NCODE / 2);

    float rnm[8];
#pragma unroll
    for (int m = 0; m < 8; m++) rnm[m] = g_rnorm[n0 + tg * 8 + m];

    // Fill Rs [64 tokens x 512 d] -> Rs[d][m]  (STS conflict-free: bank = m&31 = lane)
#pragma unroll 4
    for (int it = 0; it < 16; it++) {
        const int f  = it * 512 + tid;
        const int m  = f & 63;
        const int dg = f >> 6;            // 0..127
        const float4 v = *reinterpret_cast<const float4*>(
            &g_residual[(size_t)(n0 + m) * DIM + dg * 4]);
        Rs[(dg * 4 + 0) * 64 + m] = v.x;
        Rs[(dg * 4 + 1) * 64 + m] = v.y;
        Rs[(dg * 4 + 2) * 64 + m] = v.z;
        Rs[(dg * 4 + 3) * 64 + m] = v.w;
    }

    float bestV[8];
    int   bestI[8];
#pragma unroll
    for (int m = 0; m < 8; m++) { bestV[m] = 3.4e38f; bestI[m] = 0; }

    float4 pf[4];
    prefetch4(cb + (size_t)k0 * DIM, tid, pf);
    int buf = 0;

    for (int kc = 0; kc < NCODE / 2; kc += 256) {
        ull acc[16];
#pragma unroll
        for (int i = 0; i < 16; i++) acc[i] = 0ull;

        for (int dk = 0; dk < DIM; dk += 32) {
            float* csw = Cs + buf * CS_FLOATS;

            // Store prefetched chunk [256 codes x 32 d] into swizzled Cs[buf].
#pragma unroll
            for (int i = 0; i < 4; i++) {
                const int f  = i * 512 + tid;
                const int k  = f >> 3;
                const int dg = f & 7;
                const int kx = k ^ (dg << 2);
                const float vv[4] = {pf[i].x, pf[i].y, pf[i].z, pf[i].w};
#pragma unroll
                for (int j = 0; j < 4; j++)
                    csw[(dg * 4 + j) * 256 + kx] = vv[j];
            }

            // Prefetch next chunk while computing this one.
            {
                int nkc = kc, ndk = dk + 32;
                if (ndk == DIM) { ndk = 0; nkc = kc + 256; }
                if (nkc < NCODE / 2)
                    prefetch4(cb + (size_t)(k0 + nkc) * DIM + ndk, tid, pf);
            }
            __syncthreads();   // single barrier per chunk (double-buffered Cs)

#pragma unroll
            for (int dd = 0; dd < 32; dd++) {
                const int d = dk + dd;
                const double2* rp = reinterpret_cast<const double2*>(&Rs[d * 64 + tg * 8]);
                const double2 rA = rp[0];          // token pairs (0,1),(2,3)
                const double2 rB = rp[1];          // token pairs (4,5),(6,7)
                const ull r01 = __double_as_longlong(rA.x);
                const ull r23 = __double_as_longlong(rA.y);
                const ull r45 = __double_as_longlong(rB.x);
                const ull r67 = __double_as_longlong(rB.y);
                const float4 cv = *reinterpret_cast<const float4*>(
                    &csw[dd * 256 + (((kid ^ (dd >> 2)) & 63) << 2)]);
                const ull c0 = pack2(cv.x, cv.x);
                const ull c1 = pack2(cv.y, cv.y);
                const ull c2 = pack2(cv.z, cv.z);
                const ull c3 = pack2(cv.w, cv.w);

                fma2(acc[ 0], r01, c0); fma2(acc[ 1], r23, c0);
                fma2(acc[ 2], r45, c0); fma2(acc[ 3], r67, c0);
                fma2(acc[ 4], r01, c1); fma2(acc[ 5], r23, c1);
                fma2(acc[ 6], r45, c1); fma2(acc[ 7], r67, c1);
                fma2(acc[ 8], r01, c2); fma2(acc[ 9], r23, c2);
                fma2(acc[10], r45, c2); fma2(acc[11], r67, c2);
                fma2(acc[12], r01, c3); fma2(acc[13], r23, c3);
                fma2(acc[14], r45, c3); fma2(acc[15], r67, c3);
            }
            buf ^= 1;
        }

        // Epilogue: score = round(rnorm - 2*dot); code order ascending, strict '<'.
#pragma unroll
        for (int t = 0; t < 4; t++) {
            const int code = k0 + kc + kid * 4 + t;
#pragma unroll
            for (int p = 0; p < 4; p++) {
                const float2 s = unpack2(acc[t * 4 + p]);
                const int m0 = p * 2, m1 = p * 2 + 1;
                const float s0 = fmaf(-2.f, s.x, rnm[m0]);
                const float s1 = fmaf(-2.f, s.y, rnm[m1]);
                if (s0 < bestV[m0]) { bestV[m0] = s0; bestI[m0] = code; }
                if (s1 < bestV[m1]) { bestV[m1] = s1; bestI[m1] = code; }
            }
        }
    }

    // Warp-level (v, i) lexicographic min (lanes of a warp share the same tokens).
#pragma unroll
    for (int m = 0; m < 8; m++) {
        float v = bestV[m];
        int   i = bestI[m];
#pragma unroll
        for (int o = 16; o > 0; o >>= 1) {
            const float vo = __shfl_down_sync(0xffffffffu, v, o);
            const int   io = __shfl_down_sync(0xffffffffu, i, o);
            if (vo < v || (vo == v && io < i)) { v = vo; i = io; }
        }
        if (lane == 0) { redV[wid * 8 + m] = v; redI[wid * 8 + m] = i; }
    }
    __syncthreads();
    // Merge the two warps (code halves) of each token group.
    if (tid < 64) {
        const int tg2 = tid >> 3, m = tid & 7;
        const float v0 = redV[(tg2 * 2) * 8 + m], v1 = redV[(tg2 * 2 + 1) * 8 + m];
        const int   i0 = redI[(tg2 * 2) * 8 + m], i1 = redI[(tg2 * 2 + 1) * 8 + m];
        float v = v0; int i = i0;
        if (v1 < v || (v1 == v && i1 < i)) { v = v1; i = i1; }
        const int n = n0 + tg2 * 8 + m;
        g_pv[half * N_TOK + n] = v;
        g_pi[half * N_TOK + n] = i;
    }
}

// ------- per-token: merge halves, residual update, z_q accumulate, loss, rnorm ---
__global__ void __launch_bounds__(128)
update_kernel(const float* __restrict__ cb, int stage,
              float* __restrict__ zq, float* __restrict__ idxf)
{
    const int n = blockIdx.x;
    const int j = threadIdx.x;

    // merge two halves: half 1 wins only if strictly smaller (lower index on ties)
    const float v0 = g_pv[n], v1 = g_pv[N_TOK + n];
    const int k = (v1 < v0) ? g_pi[N_TOK + n] : g_pi[n];
    if (j == 0) idxf[(size_t)n * NQ + stage] = (float)k;

    const size_t off = (size_t)n * DIM + j * 4;
    const float4 r = *reinterpret_cast<float4*>(&g_residual[off]);
    const float4 c = *reinterpret_cast<const float4*>(&cb[(size_t)k * DIM + j * 4]);

    const float4 rn = make_float4(r.x - c.x, r.y - c.y, r.z - c.z, r.w - c.w);
    if (stage < NQ - 1)
        *reinterpret_cast<float4*>(&g_residual[off]) = rn;

    float4 zo;
    if (stage == 0) {
        zo = c;
    } else {
        zo = *reinterpret_cast<float4*>(&zq[off]);
        zo.x += c.x; zo.y += c.y; zo.z += c.z; zo.w += c.w;
    }
    *reinterpret_cast<float4*>(&zq[off]) = zo;

    // next-stage rnorm + loss on UPDATED residual: (c - r_new)^2
    float rs = fmaf(rn.x, rn.x, fmaf(rn.y, rn.y, fmaf(rn.z, rn.z, rn.w * rn.w)));
    const float4 tt = make_float4(c.x - rn.x, c.y - rn.y, c.z - rn.z, c.w - rn.w);
    float ls = tt.x * tt.x + tt.y * tt.y + tt.z * tt.z + tt.w * tt.w;
#pragma unroll
    for (int o = 16; o > 0; o >>= 1) {
        rs += __shfl_down_sync(0xffffffffu, rs, o);
        ls += __shfl_down_sync(0xffffffffu, ls, o);
    }
    __shared__ float wr[4], wl[4];
    if ((j & 31) == 0) { wr[j >> 5] = rs; wl[j >> 5] = ls; }
    __syncthreads();
    if (j == 0) {
        if (stage < NQ - 1) g_rnorm[n] = (wr[0] + wr[1]) + (wr[2] + wr[3]);
        atomicAdd(&g_loss[stage], (double)((wl[0] + wl[1]) + (wl[2] + wl[3])));
    }
}

// ---------------- straight-through: z_q = z + (z_q - z), reference fp order -----
__global__ void __launch_bounds__(256)
ste_kernel(const float* __restrict__ z, float* __restrict__ zq)
{
    const int t = blockIdx.x * 256 + threadIdx.x;
    const float4 zv = reinterpret_cast<const float4*>(z)[t];
    float4 q = reinterpret_cast<float4*>(zq)[t];
    q.x = zv.x + (q.x - zv.x);
    q.y = zv.y + (q.y - zv.y);
    q.z = zv.z + (q.z - zv.z);
    q.w = zv.w + (q.w - zv.w);
    reinterpret_cast<float4*>(zq)[t] = q;
}

// ------- init: residual = z, rnorm(z), loss reset (one block per token) ---------
__global__ void __launch_bounds__(128)
init_kernel(const float* __restrict__ z)
{
    const int n = blockIdx.x;
    const int j = threadIdx.x;
    if (n == 0 && j < NQ) g_loss[j] = 0.0;
    const size_t off = (size_t)n * DIM + j * 4;
    const float4 v = *reinterpret_cast<const float4*>(&z[off]);
    *reinterpret_cast<float4*>(&g_residual[off]) = v;
    float rs = fmaf(v.x, v.x, fmaf(v.y, v.y, fmaf(v.z, v.z, v.w * v.w)));
#pragma unroll
    for (int o = 16; o > 0; o >>= 1) rs += __shfl_down_sync(0xffffffffu, rs, o);
    __shared__ float wr[4];
    if ((j & 31) == 0) wr[j >> 5] = rs;
    __syncthreads();
    if (j == 0) g_rnorm[n] = (wr[0] + wr[1]) + (wr[2] + wr[3]);
}

__global__ void finalize_kernel(float* __restrict__ outloss)
{
    double t = 0.0;
#pragma unroll
    for (int s = 0; s < NQ; s++) t += 1.25 * (g_loss[s] / 16777216.0);
    *outloss = (float)t;
}

// ---------------- launch --------------------------------------------------------
extern "C" void kernel_launch(void* const* d_in, const int* in_sizes, int n_in,
                              void* d_out, int out_size)
{
    const float* z   = (const float*)d_in[0];   // [16,2048,512] f32
    const float* cbs = (const float*)d_in[1];   // [4,4096,512]  f32
    float* out   = (float*)d_out;
    float* zq    = out;                                       // 16,777,216
    float* idxf  = out + (size_t)N_TOK * DIM;                 // 131,072
    float* lossp = idxf + (size_t)N_TOK * NQ;                 // 1

    cudaFuncSetAttribute(argmin_kernel,
                         cudaFuncAttributeMaxDynamicSharedMemorySize, SMEM_BYTES);

    init_kernel<<<N_TOK, 128>>>(z);

    for (int s = 0; s < NQ; s++) {
        const float* cb_s = cbs + (size_t)s * NCODE * DIM;
        argmin_kernel<<<(N_TOK / 64) * 2, 512, SMEM_BYTES>>>(cb_s);
        update_kernel<<<N_TOK, 128>>>(cb_s, s, zq, idxf);
    }
    ste_kernel<<<(N_TOK * DIM / 4) / 256, 256>>>(z, zq);
    finalize_kernel<<<1, 1>>>(lossp);
}

// round 6
// speedup vs baseline: 1.7446x; 1.0325x over previous
#include <cuda_runtime.h>
#include <cstdint>
#include <cstddef>

#define N_TOK 32768
#define DIM   512
#define NCODE 4096
#define NQ    4

typedef unsigned long long ull;

// ---------------- device-global scratch (no allocations allowed) ----------------
__device__ float  g_residual[N_TOK * DIM];   // 64 MB
__device__ float  g_rnorm[N_TOK];            // per-token ||r||^2 (fp32), per stage
__device__ float  g_pv[2 * N_TOK];           // per-half best value
__device__ int    g_pi[2 * N_TOK];           // per-half best index
__device__ double g_loss[NQ];

// ---------------- packed f32x2 helpers (FFMA2 is PTX-only on sm_103a) -----------
__device__ __forceinline__ ull pack2(float a, float b) {
    ull r;
    asm("mov.b64 %0, {%1,%2};" : "=l"(r) : "f"(a), "f"(b));
    return r;
}
__device__ __forceinline__ void fma2(ull& d, ull a, ull b) {
    asm("fma.rn.f32x2 %0, %1, %2, %0;" : "+l"(d) : "l"(a), "l"(b));
}
__device__ __forceinline__ float2 unpack2(ull v) {
    float lo, hi;
    asm("mov.b64 {%0,%1}, %2;" : "=f"(lo), "=f"(hi) : "l"(v));
    return make_float2(lo, hi);
}

// smem: Rs[512][64] + Cs[2 groups][2 bufs][32][128] + red arrays
#define RS_FLOATS 32768
#define CS_FLOATS 4096                       // one buffer: 32 d x 128 codes
#define RED_OFF   (RS_FLOATS + 4 * CS_FLOATS)          // 49152
#define SMEM_FLOATS (RED_OFF + 128 + 128)
#define SMEM_BYTES  (SMEM_FLOATS * 4)

// prefetch one [128 codes x 32 d] chunk: 4 float4 per thread (256 threads/group)
__device__ __forceinline__ void prefetch4(const float* __restrict__ p, int gt,
                                          float4* pf) {
#pragma unroll
    for (int i = 0; i < 4; i++) {
        const int f  = i * 256 + gt;
        const int k  = f >> 3;     // code 0..127
        const int dg = f & 7;      // d-group 0..7
        pf[i] = *reinterpret_cast<const float4*>(&p[(size_t)k * DIM + dg * 4]);
    }
}

// ---------------- fused GEMM + argmin -------------------------------------------
// One block = 64 tokens x 2048 codes (half codebook). 512 threads in TWO
// independent 8-warp groups (named barriers) covering codes [0,1024) and
// [1024,2048) of the half, each with private double-buffered Cs chunks.
// Per warp: 8 tokens (warp&7), lanes = 32 code-quads of a 128-code chunk.
// Numerics identical to reference: per (token,code) dot is a sequential-d
// fp32 FMA chain; score = fmaf(-2, dot, rnorm); tie-break lowest index.
__global__ void __launch_bounds__(512, 1)
argmin_kernel(const float* __restrict__ cb)   // codebook for this stage [NCODE][DIM]
{
    extern __shared__ float sm[];
    float* Rs   = sm;                 // [512][64]  Rs[d*64+m]
    float* Cs   = sm + RS_FLOATS;     // 4 buffers of [32][128], swizzled
    float* redV = sm + RED_OFF;       // [16 warps][8 tokens]
    int*   redI = (int*)(redV + 128);

    const int tid  = threadIdx.x;
    const int grp  = tid >> 8;        // 0,1: independent barrier domains
    const int gt   = tid & 255;       // thread id within group
    const int tg   = gt >> 5;         // warp-in-group = token group 0..7
    const int lane = tid & 31;
    const int wid  = tid >> 5;
    const int n0   = (blockIdx.x >> 1) * 64;
    const int half = blockIdx.x & 1;
    const int k0   = half * (NCODE / 2) + grp * 1024;

    float rnm[8];
#pragma unroll
    for (int m = 0; m < 8; m++) rnm[m] = g_rnorm[n0 + tg * 8 + m];

    // Fill Rs [64 tokens x 512 d] -> Rs[d][m] (all 512 threads; STS bank = lane)
#pragma unroll 4
    for (int it = 0; it < 16; it++) {
        const int f  = it * 512 + tid;
        const int m  = f & 63;
        const int dg = f >> 6;            // 0..127
        const float4 v = *reinterpret_cast<const float4*>(
            &g_residual[(size_t)(n0 + m) * DIM + dg * 4]);
        Rs[(dg * 4 + 0) * 64 + m] = v.x;
        Rs[(dg * 4 + 1) * 64 + m] = v.y;
        Rs[(dg * 4 + 2) * 64 + m] = v.z;
        Rs[(dg * 4 + 3) * 64 + m] = v.w;
    }
    __syncthreads();                 // Rs ready for both groups

    float bestV[8];
    int   bestI[8];
#pragma unroll
    for (int m = 0; m < 8; m++) { bestV[m] = 3.4e38f; bestI[m] = 0; }

    float4 pf[4];
    prefetch4(cb + (size_t)k0 * DIM, gt, pf);
    int buf = 0;

    for (int kc = 0; kc < 1024; kc += 128) {
        ull acc[16];
#pragma unroll
        for (int i = 0; i < 16; i++) acc[i] = 0ull;

        for (int dk = 0; dk < DIM; dk += 32) {
            float* csw = Cs + (grp * 2 + buf) * CS_FLOATS;

            // Store prefetched chunk [128 codes x 32 d] into swizzled Cs.
            // layout: csw[d*128 + (k ^ ((d>>2)<<2))]
#pragma unroll
            for (int i = 0; i < 4; i++) {
                const int f  = i * 256 + gt;
                const int k  = f >> 3;
                const int dg = f & 7;
                const int kx = k ^ (dg << 2);
                const float vv[4] = {pf[i].x, pf[i].y, pf[i].z, pf[i].w};
#pragma unroll
                for (int j = 0; j < 4; j++)
                    csw[(dg * 4 + j) * 128 + kx] = vv[j];
            }

            // Prefetch next chunk while computing this one.
            {
                int nkc = kc, ndk = dk + 32;
                if (ndk == DIM) { ndk = 0; nkc = kc + 128; }
                if (nkc < 1024)
                    prefetch4(cb + (size_t)(k0 + nkc) * DIM + ndk, gt, pf);
            }
            // group-private barrier (double-buffered Cs -> one barrier/chunk)
            asm volatile("bar.sync %0, 256;" :: "r"(grp + 1) : "memory");

#pragma unroll
            for (int dd = 0; dd < 32; dd++) {
                const int d = dk + dd;
                const double2* rp = reinterpret_cast<const double2*>(&Rs[d * 64 + tg * 8]);
                const double2 rA = rp[0];          // token pairs (0,1),(2,3)
                const double2 rB = rp[1];          // token pairs (4,5),(6,7)
                const ull r01 = __double_as_longlong(rA.x);
                const ull r23 = __double_as_longlong(rA.y);
                const ull r45 = __double_as_longlong(rB.x);
                const ull r67 = __double_as_longlong(rB.y);
                const float4 cv = *reinterpret_cast<const float4*>(
                    &csw[dd * 128 + (((lane ^ (dd >> 2)) & 31) << 2)]);
                const ull c0 = pack2(cv.x, cv.x);
                const ull c1 = pack2(cv.y, cv.y);
                const ull c2 = pack2(cv.z, cv.z);
                const ull c3 = pack2(cv.w, cv.w);

                fma2(acc[ 0], r01, c0); fma2(acc[ 1], r23, c0);
                fma2(acc[ 2], r45, c0); fma2(acc[ 3], r67, c0);
                fma2(acc[ 4], r01, c1); fma2(acc[ 5], r23, c1);
                fma2(acc[ 6], r45, c1); fma2(acc[ 7], r67, c1);
                fma2(acc[ 8], r01, c2); fma2(acc[ 9], r23, c2);
                fma2(acc[10], r45, c2); fma2(acc[11], r67, c2);
                fma2(acc[12], r01, c3); fma2(acc[13], r23, c3);
                fma2(acc[14], r45, c3); fma2(acc[15], r67, c3);
            }
            buf ^= 1;
        }

        // Epilogue: score = round(rnorm - 2*dot); ascending code, strict '<'.
#pragma unroll
        for (int t = 0; t < 4; t++) {
            const int code = k0 + kc + lane * 4 + t;
#pragma unroll
            for (int p = 0; p < 4; p++) {
                const float2 s = unpack2(acc[t * 4 + p]);
                const int m0 = p * 2, m1 = p * 2 + 1;
                const float s0 = fmaf(-2.f, s.x, rnm[m0]);
                const float s1 = fmaf(-2.f, s.y, rnm[m1]);
                if (s0 < bestV[m0]) { bestV[m0] = s0; bestI[m0] = code; }
                if (s1 < bestV[m1]) { bestV[m1] = s1; bestI[m1] = code; }
            }
        }
    }

    // Warp-level (v, i) lexicographic min (lanes of a warp share the same tokens).
#pragma unroll
    for (int m = 0; m < 8; m++) {
        float v = bestV[m];
        int   i = bestI[m];
#pragma unroll
        for (int o = 16; o > 0; o >>= 1) {
            const float vo = __shfl_down_sync(0xffffffffu, v, o);
            const int   io = __shfl_down_sync(0xffffffffu, i, o);
            if (vo < v || (vo == v && io < i)) { v = vo; i = io; }
        }
        if (lane == 0) { redV[wid * 8 + m] = v; redI[wid * 8 + m] = i; }
    }
    __syncthreads();
    // Merge the two groups (code sub-ranges) of each token; group0 = lower codes.
    if (tid < 64) {
        const int tg2 = tid >> 3, m = tid & 7;
        const float v0 = redV[tg2 * 8 + m],        v1 = redV[64 + tg2 * 8 + m];
        const int   i0 = redI[tg2 * 8 + m],        i1 = redI[64 + tg2 * 8 + m];
        float v = v0; int i = i0;
        if (v1 < v || (v1 == v && i1 < i)) { v = v1; i = i1; }
        const int n = n0 + tg2 * 8 + m;
        g_pv[half * N_TOK + n] = v;
        g_pi[half * N_TOK + n] = i;
    }
}

// ------- per-token: merge halves, residual update, z_q accumulate, loss, rnorm ---
__global__ void __launch_bounds__(128)
update_kernel(const float* __restrict__ cb, int stage,
              float* __restrict__ zq, float* __restrict__ idxf)
{
    const int n = blockIdx.x;
    const int j = threadIdx.x;

    // merge two halves: half 1 wins only if strictly smaller (lower index on ties)
    const float v0 = g_pv[n], v1 = g_pv[N_TOK + n];
    const int k = (v1 < v0) ? g_pi[N_TOK + n] : g_pi[n];
    if (j == 0) idxf[(size_t)n * NQ + stage] = (float)k;

    const size_t off = (size_t)n * DIM + j * 4;
    const float4 r = *reinterpret_cast<float4*>(&g_residual[off]);
    const float4 c = *reinterpret_cast<const float4*>(&cb[(size_t)k * DIM + j * 4]);

    const float4 rn = make_float4(r.x - c.x, r.y - c.y, r.z - c.z, r.w - c.w);
    if (stage < NQ - 1)
        *reinterpret_cast<float4*>(&g_residual[off]) = rn;

    float4 zo;
    if (stage == 0) {
        zo = c;
    } else {
        zo = *reinterpret_cast<float4*>(&zq[off]);
        zo.x += c.x; zo.y += c.y; zo.z += c.z; zo.w += c.w;
    }
    *reinterpret_cast<float4*>(&zq[off]) = zo;

    // next-stage rnorm + loss on UPDATED residual: (c - r_new)^2
    float rs = fmaf(rn.x, rn.x, fmaf(rn.y, rn.y, fmaf(rn.z, rn.z, rn.w * rn.w)));
    const float4 tt = make_float4(c.x - rn.x, c.y - rn.y, c.z - rn.z, c.w - rn.w);
    float ls = tt.x * tt.x + tt.y * tt.y + tt.z * tt.z + tt.w * tt.w;
#pragma unroll
    for (int o = 16; o > 0; o >>= 1) {
        rs += __shfl_down_sync(0xffffffffu, rs, o);
        ls += __shfl_down_sync(0xffffffffu, ls, o);
    }
    __shared__ float wr[4], wl[4];
    if ((j & 31) == 0) { wr[j >> 5] = rs; wl[j >> 5] = ls; }
    __syncthreads();
    if (j == 0) {
        if (stage < NQ - 1) g_rnorm[n] = (wr[0] + wr[1]) + (wr[2] + wr[3]);
        atomicAdd(&g_loss[stage], (double)((wl[0] + wl[1]) + (wl[2] + wl[3])));
    }
}

// ---------------- straight-through: z_q = z + (z_q - z), reference fp order -----
__global__ void __launch_bounds__(256)
ste_kernel(const float* __restrict__ z, float* __restrict__ zq)
{
    const int t = blockIdx.x * 256 + threadIdx.x;
    const float4 zv = reinterpret_cast<const float4*>(z)[t];
    float4 q = reinterpret_cast<float4*>(zq)[t];
    q.x = zv.x + (q.x - zv.x);
    q.y = zv.y + (q.y - zv.y);
    q.z = zv.z + (q.z - zv.z);
    q.w = zv.w + (q.w - zv.w);
    reinterpret_cast<float4*>(zq)[t] = q;
}

// ------- init: residual = z, rnorm(z), loss reset (one block per token) ---------
__global__ void __launch_bounds__(128)
init_kernel(const float* __restrict__ z)
{
    const int n = blockIdx.x;
    const int j = threadIdx.x;
    if (n == 0 && j < NQ) g_loss[j] = 0.0;
    const size_t off = (size_t)n * DIM + j * 4;
    const float4 v = *reinterpret_cast<const float4*>(&z[off]);
    *reinterpret_cast<float4*>(&g_residual[off]) = v;
    float rs = fmaf(v.x, v.x, fmaf(v.y, v.y, fmaf(v.z, v.z, v.w * v.w)));
#pragma unroll
    for (int o = 16; o > 0; o >>= 1) rs += __shfl_down_sync(0xffffffffu, rs, o);
    __shared__ float wr[4];
    if ((j & 31) == 0) wr[j >> 5] = rs;
    __syncthreads();
    if (j == 0) g_rnorm[n] = (wr[0] + wr[1]) + (wr[2] + wr[3]);
}

__global__ void finalize_kernel(float* __restrict__ outloss)
{
    double t = 0.0;
#pragma unroll
    for (int s = 0; s < NQ; s++) t += 1.25 * (g_loss[s] / 16777216.0);
    *outloss = (float)t;
}

// ---------------- launch --------------------------------------------------------
extern "C" void kernel_launch(void* const* d_in, const int* in_sizes, int n_in,
                              void* d_out, int out_size)
{
    const float* z   = (const float*)d_in[0];   // [16,2048,512] f32
    const float* cbs = (const float*)d_in[1];   // [4,4096,512]  f32
    float* out   = (float*)d_out;
    float* zq    = out;                                       // 16,777,216
    float* idxf  = out + (size_t)N_TOK * DIM;                 // 131,072
    float* lossp = idxf + (size_t)N_TOK * NQ;                 // 1

    cudaFuncSetAttribute(argmin_kernel,
                         cudaFuncAttributeMaxDynamicSharedMemorySize, SMEM_BYTES);

    init_kernel<<<N_TOK, 128>>>(z);

    for (int s = 0; s < NQ; s++) {
        const float* cb_s = cbs + (size_t)s * NCODE * DIM;
        argmin_kernel<<<(N_TOK / 64) * 2, 512, SMEM_BYTES>>>(cb_s);
        update_kernel<<<N_TOK, 128>>>(cb_s, s, zq, idxf);
    }
    ste_kernel<<<(N_TOK * DIM / 4) / 256, 256>>>(z, zq);
    finalize_kernel<<<1, 1>>>(lossp);
}